// round 10
// baseline (speedup 1.0000x reference)
#include <cuda_runtime.h>
#include <cuda_fp16.h>
#include <cstdint>

#define D_MODEL 1024
#define NHEADS  16
#define HD      64
#define BATCH   2
#define TSEQ    2048
#define M_TOT   (BATCH * TSEQ)   // 4096

// Scratch (allocation-free rule: __device__ globals).
__device__ float g_Q[BATCH * NHEADS * TSEQ * HD];
__device__ float g_K[BATCH * NHEADS * TSEQ * HD];
__device__ float g_V[BATCH * NHEADS * TSEQ * HD];
__device__ float g_A[BATCH * TSEQ * D_MODEL];

static __device__ __forceinline__ uint32_t smem_u32(const void* p) {
    uint32_t a;
    asm("{ .reg .u64 t; cvta.to.shared.u64 t, %1; cvt.u32.u64 %0, t; }"
        : "=r"(a) : "l"(p));
    return a;
}

__device__ __forceinline__ void ldsm_x4(unsigned& r0, unsigned& r1,
                                        unsigned& r2, unsigned& r3,
                                        unsigned addr)
{
    asm volatile("ldmatrix.sync.aligned.m8n8.x4.shared.b16 {%0,%1,%2,%3}, [%4];"
                 : "=r"(r0), "=r"(r1), "=r"(r2), "=r"(r3) : "r"(addr));
}

__device__ __forceinline__ void ldsm_x4_t(unsigned& r0, unsigned& r1,
                                          unsigned& r2, unsigned& r3,
                                          unsigned addr)
{
    asm volatile("ldmatrix.sync.aligned.m8n8.x4.trans.shared.b16 {%0,%1,%2,%3}, [%4];"
                 : "=r"(r0), "=r"(r1), "=r"(r2), "=r"(r3) : "r"(addr));
}

__device__ __forceinline__ void mma_f16(float* d, const unsigned* a,
                                        unsigned b0, unsigned b1)
{
    asm volatile(
        "mma.sync.aligned.m16n8k16.row.col.f32.f16.f16.f32 "
        "{%0,%1,%2,%3}, {%4,%5,%6,%7}, {%8,%9}, {%0,%1,%2,%3};"
        : "+f"(d[0]), "+f"(d[1]), "+f"(d[2]), "+f"(d[3])
        : "r"(a[0]), "r"(a[1]), "r"(a[2]), "r"(a[3]), "r"(b0), "r"(b1));
}

static __device__ __forceinline__ unsigned packh2(float x, float y)
{
    __half2 h = __floats2half2_rn(x, y);
    return *(unsigned*)&h;
}

// ===========================================================================
// Projection GEMMs: 2-term fp16 split.  Y = Xhi*W + Xlo*W  (W single fp16).
// Block 128x128x16, 256 threads (8 warps = 2m x 4n), warp tile 64x32.
// A smem row: 80B = 32B hi | 32B lo | 16B pad (conflict-free ldmatrix).
// B smem row: 48B = 32B fp16 | 16B pad (48-stride phases verified disjoint).
// ===========================================================================
#define AROW_BYTES 80
#define BROW_BYTES 48
#define A_STAGE (128 * AROW_BYTES)   // 10240
#define B_STAGE (128 * BROW_BYTES)   // 6144
#define SMEM_TOTAL (2 * A_STAGE + 2 * B_STAGE)   // 32768

// X: 8 fp32 -> 4 half2 hi + 4 half2 lo (residual)
__device__ __forceinline__ void cvt8_store_a(unsigned addr, float4 a, float4 b)
{
    float f[8] = {a.x, a.y, a.z, a.w, b.x, b.y, b.z, b.w};
    unsigned hi[4], lo[4];
    #pragma unroll
    for (int i = 0; i < 4; i++) {
        float x = f[2 * i], y = f[2 * i + 1];
        __half2 hp = __floats2half2_rn(x, y);
        float lx = x - __low2float(hp), ly = y - __high2float(hp);
        __half2 lp = __floats2half2_rn(lx, ly);
        hi[i] = *(unsigned*)&hp;
        lo[i] = *(unsigned*)&lp;
    }
    asm volatile("st.shared.v4.b32 [%0], {%1,%2,%3,%4};"
                 :: "r"(addr), "r"(hi[0]), "r"(hi[1]), "r"(hi[2]), "r"(hi[3]));
    asm volatile("st.shared.v4.b32 [%0], {%1,%2,%3,%4};"
                 :: "r"(addr + 32), "r"(lo[0]), "r"(lo[1]), "r"(lo[2]), "r"(lo[3]));
}

// W: 8 fp32 -> 4 half2
__device__ __forceinline__ void cvt8_store_b(unsigned addr, float4 a, float4 b)
{
    unsigned h0 = packh2(a.x, a.y), h1 = packh2(a.z, a.w);
    unsigned h2 = packh2(b.x, b.y), h3 = packh2(b.z, b.w);
    asm volatile("st.shared.v4.b32 [%0], {%1,%2,%3,%4};"
                 :: "r"(addr), "r"(h0), "r"(h1), "r"(h2), "r"(h3));
}

__device__ __forceinline__ void mma_core(
    const float* __restrict__ X, const float* __restrict__ W,
    int m0, int n0, char* smem, float acc[4][4][4])
{
    const int tid  = threadIdx.x;
    const int lane = tid & 31;
    const int warp = tid >> 5;
    const int wm0  = (warp >> 2) * 64;
    const int wn0  = (warp & 3) * 32;

    const int lrow  = tid >> 1;
    const int lhalf = tid & 1;

    const float* xp = X + (size_t)(m0 + lrow) * D_MODEL + lhalf * 8;
    const float* wp = W + (size_t)(n0 + lrow) * D_MODEL + lhalf * 8;

    const unsigned sAb = smem_u32(smem);
    const unsigned sBb = sAb + 2 * A_STAGE;

    const unsigned stA = sAb + lrow * AROW_BYTES + lhalf * 16;
    const unsigned stB = sBb + lrow * BROW_BYTES + lhalf * 16;

    const int arow  = lane & 15;
    const int acoff = (lane >> 4) << 4;
    const unsigned ldA = sAb + (unsigned)(wm0 + arow) * AROW_BYTES + acoff;
    const int brow  = (lane & 7) + ((lane >> 4) << 3);
    const int bcoff = ((lane >> 3) & 1) << 4;
    const unsigned ldB = sBb + (unsigned)(wn0 + brow) * BROW_BYTES + bcoff;

    {
        float4 x0 = *(const float4*)xp;
        float4 x1 = *(const float4*)(xp + 4);
        float4 w0 = *(const float4*)wp;
        float4 w1 = *(const float4*)(wp + 4);
        cvt8_store_a(stA, x0, x1);
        cvt8_store_b(stB, w0, w1);
    }
    __syncthreads();

    unsigned buf = 0;
    for (int k0 = 16; k0 <= D_MODEL; k0 += 16) {
        const bool more = (k0 < D_MODEL);
        float4 nx0, nx1, nw0, nw1;
        if (more) {
            nx0 = *(const float4*)(xp + k0);
            nx1 = *(const float4*)(xp + k0 + 4);
            nw0 = *(const float4*)(wp + k0);
            nw1 = *(const float4*)(wp + k0 + 4);
        }

        const unsigned offA = buf * A_STAGE;
        const unsigned offB = buf * B_STAGE;
        unsigned b0[4], b1[4];
        ldsm_x4(b0[0], b0[1], b0[2], b0[3], ldB + offB);                   // n0,n1
        ldsm_x4(b1[0], b1[1], b1[2], b1[3], ldB + offB + 16 * BROW_BYTES); // n2,n3

        #pragma unroll
        for (int mi = 0; mi < 4; mi++) {
            unsigned ah[4], al[4];
            const unsigned am = ldA + offA + (unsigned)(mi * 16) * AROW_BYTES;
            ldsm_x4(ah[0], ah[1], ah[2], ah[3], am);
            ldsm_x4(al[0], al[1], al[2], al[3], am + 32);
            mma_f16(acc[mi][0], ah, b0[0], b0[1]);
            mma_f16(acc[mi][0], al, b0[0], b0[1]);
            mma_f16(acc[mi][1], ah, b0[2], b0[3]);
            mma_f16(acc[mi][1], al, b0[2], b0[3]);
            mma_f16(acc[mi][2], ah, b1[0], b1[1]);
            mma_f16(acc[mi][2], al, b1[0], b1[1]);
            mma_f16(acc[mi][3], ah, b1[2], b1[3]);
            mma_f16(acc[mi][3], al, b1[2], b1[3]);
        }

        if (more) {
            cvt8_store_a(stA + (buf ^ 1u) * A_STAGE, nx0, nx1);
            cvt8_store_b(stB + (buf ^ 1u) * B_STAGE, nw0, nw1);
            __syncthreads();
            buf ^= 1u;
        }
    }
}

__global__ __launch_bounds__(256)
void qkv_gemm_kernel(const float* __restrict__ X,
                     const float* __restrict__ Wq, const float* __restrict__ bq,
                     const float* __restrict__ Wk, const float* __restrict__ bk,
                     const float* __restrict__ Wv, const float* __restrict__ bv)
{
    __shared__ __align__(16) char smem[SMEM_TOTAL];

    const float* W; const float* bias; float* dst;
    if (blockIdx.z == 0)      { W = Wq; bias = bq; dst = g_Q; }
    else if (blockIdx.z == 1) { W = Wk; bias = bk; dst = g_K; }
    else                      { W = Wv; bias = bv; dst = g_V; }

    const int m0 = blockIdx.y * 128, n0 = blockIdx.x * 128;
    float acc[4][4][4];
    #pragma unroll
    for (int i = 0; i < 4; i++)
        #pragma unroll
        for (int j = 0; j < 4; j++)
            #pragma unroll
            for (int r = 0; r < 4; r++) acc[i][j][r] = 0.f;

    mma_core(X, W, m0, n0, smem, acc);

    const int lane = threadIdx.x & 31, warp = threadIdx.x >> 5;
    const int wm0 = (warp >> 2) * 64, wn0 = (warp & 3) * 32;
    const int g = lane >> 2, t = lane & 3;

    #pragma unroll
    for (int n8 = 0; n8 < 4; n8++) {
        const int n = n0 + wn0 + n8 * 8 + 2 * t;
        const float bx = bias[n], by = bias[n + 1];
        const int h = n >> 6, d = n & 63;
        #pragma unroll
        for (int mi = 0; mi < 4; mi++) {
            #pragma unroll
            for (int half = 0; half < 2; half++) {
                const int m = m0 + wm0 + mi * 16 + g + half * 8;
                const int b = m >> 11, tt = m & (TSEQ - 1);
                float2 v;
                v.x = acc[mi][n8][2 * half + 0] + bx;
                v.y = acc[mi][n8][2 * half + 1] + by;
                *(float2*)&dst[(((size_t)b * NHEADS + h) * TSEQ + tt) * HD + d] = v;
            }
        }
    }
}

__global__ __launch_bounds__(256)
void out_gemm_kernel(const float* __restrict__ Wo, const float* __restrict__ bo,
                     float* __restrict__ Y)
{
    __shared__ __align__(16) char smem[SMEM_TOTAL];

    const int m0 = blockIdx.y * 128, n0 = blockIdx.x * 128;
    float acc[4][4][4];
    #pragma unroll
    for (int i = 0; i < 4; i++)
        #pragma unroll
        for (int j = 0; j < 4; j++)
            #pragma unroll
            for (int r = 0; r < 4; r++) acc[i][j][r] = 0.f;

    mma_core(g_A, Wo, m0, n0, smem, acc);

    const int lane = threadIdx.x & 31, warp = threadIdx.x >> 5;
    const int wm0 = (warp >> 2) * 64, wn0 = (warp & 3) * 32;
    const int g = lane >> 2, t = lane & 3;

    #pragma unroll
    for (int n8 = 0; n8 < 4; n8++) {
        const int n = n0 + wn0 + n8 * 8 + 2 * t;
        const float bx = bo[n], by = bo[n + 1];
        #pragma unroll
        for (int mi = 0; mi < 4; mi++) {
            #pragma unroll
            for (int half = 0; half < 2; half++) {
                const int m = m0 + wm0 + mi * 16 + g + half * 8;
                float2 v;
                v.x = acc[mi][n8][2 * half + 0] + bx;
                v.y = acc[mi][n8][2 * half + 1] + by;
                *(float2*)&Y[(size_t)m * D_MODEL + n] = v;
            }
        }
    }
}

// ===========================================================================
// MMA flash-attention, single fp16 (errors ~1e-4, harmless through softmax).
// grid (T/64=32, B*H=32), 128 threads = 4 warps; warp w owns 16 query rows.
// Key tiles jt in [qt-2, qt] (decay -(i-j): delta >= 129 underflows to 0,
// identical to reference). smem: 64x64 fp16 tiles, 128B rows, SW128 swizzle.
// ===========================================================================

static __device__ __forceinline__ void cvt_store32h(
    uint32_t buf, int row, int half, const float* gp)
{
    uint32_t base_off = (uint32_t)row * 128u + (uint32_t)half * 64u;
    #pragma unroll
    for (int i = 0; i < 4; i++) {
        float4 va = *(const float4*)(gp + i * 8);
        float4 vb = *(const float4*)(gp + i * 8 + 4);
        unsigned h0 = packh2(va.x, va.y), h1 = packh2(va.z, va.w);
        unsigned h2 = packh2(vb.x, vb.y), h3 = packh2(vb.z, vb.w);
        uint32_t off = base_off + (uint32_t)i * 16u;
        uint32_t sw = off ^ ((off >> 3) & 0x70u);
        asm volatile("st.shared.v4.b32 [%0], {%1,%2,%3,%4};"
                     :: "r"(buf + sw), "r"(h0), "r"(h1), "r"(h2), "r"(h3));
    }
}

__global__ __launch_bounds__(128)
void attn_mma_kernel()
{
    __shared__ __align__(16) char sQ[8192];
    __shared__ __align__(16) char sK[8192];
    __shared__ __align__(16) char sV[8192];

    const int tid  = threadIdx.x;
    const int lane = tid & 31;
    const int warp = tid >> 5;
    const int qt   = blockIdx.x;
    const int bh   = blockIdx.y;

    const uint32_t uQ = smem_u32(sQ);
    const uint32_t uK = smem_u32(sK);
    const uint32_t uV = smem_u32(sV);

    const float* Qg = g_Q + (size_t)bh * TSEQ * HD;
    const float* Kg = g_K + (size_t)bh * TSEQ * HD;
    const float* Vg = g_V + (size_t)bh * TSEQ * HD;

    const int lrow  = tid >> 1;   // 0..63
    const int lhalf = tid & 1;

    // ---- stage Q tile, load Q fragments (held in regs for all ktiles) ----
    cvt_store32h(uQ, lrow, lhalf,
                 Qg + ((size_t)qt * 64 + lrow) * HD + lhalf * 32);
    __syncthreads();

    unsigned qh[4][4];
    {
        const int qrow = warp * 16 + (lane & 15);
        const int sel  = qrow & 7;
        #pragma unroll
        for (int ks = 0; ks < 4; ks++) {
            const int c16 = ks * 2 + (lane >> 4);
            const unsigned a = (unsigned)qrow * 128u + (unsigned)((c16 ^ sel) << 4);
            ldsm_x4(qh[ks][0], qh[ks][1], qh[ks][2], qh[ks][3], uQ + a);
        }
    }

    // ldmatrix lane geometry for K (no trans) and V (trans)
    const int krow_b = (lane & 7) + ((lane >> 4) << 3);
    const int kc16_b = (lane >> 3) & 1;
    const int vrow_b = (lane & 7) + (((lane >> 3) & 1) << 3);
    const int vc16_b = lane >> 4;

    float o[8][4];
    #pragma unroll
    for (int i = 0; i < 8; i++)
        #pragma unroll
        for (int r = 0; r < 4; r++) o[i][r] = 0.f;
    float m0r = -1e30f, m1r = -1e30f, l0 = 0.f, l1 = 0.f;

    const int jt0 = (qt >= 2) ? (qt - 2) : 0;
    for (int jt = jt0; jt <= qt; jt++) {
        __syncthreads();
        cvt_store32h(uK, lrow, lhalf,
                     Kg + ((size_t)jt * 64 + lrow) * HD + lhalf * 32);
        cvt_store32h(uV, lrow, lhalf,
                     Vg + ((size_t)jt * 64 + lrow) * HD + lhalf * 32);
        __syncthreads();

        // ---- S = Q K^T ----
        float s[8][4];
        #pragma unroll
        for (int i = 0; i < 8; i++)
            #pragma unroll
            for (int r = 0; r < 4; r++) s[i][r] = 0.f;

        #pragma unroll
        for (int ng = 0; ng < 4; ng++) {
            #pragma unroll
            for (int ks = 0; ks < 4; ks++) {
                const int jr = ng * 16 + krow_b;
                const int c16 = ks * 2 + kc16_b;
                const unsigned a = (unsigned)jr * 128u
                                 + (unsigned)((c16 ^ (jr & 7)) << 4);
                unsigned kh[4];
                ldsm_x4(kh[0], kh[1], kh[2], kh[3], uK + a);
                mma_f16(s[ng * 2],     qh[ks], kh[0], kh[1]);
                mma_f16(s[ng * 2 + 1], qh[ks], kh[2], kh[3]);
            }
        }

        // ---- softmax (online) ----
        const int dbase = (qt - jt) * 64 + warp * 16 + (lane >> 2);
        float rmax0 = -1e30f, rmax1 = -1e30f;
        #pragma unroll
        for (int n8 = 0; n8 < 8; n8++) {
            const int d0 = dbase - (n8 * 8 + (lane & 3) * 2);
            s[n8][0] = (d0     >= 0) ? s[n8][0] * 0.125f - (float)d0       : -1e30f;
            s[n8][1] = (d0 - 1 >= 0) ? s[n8][1] * 0.125f - (float)(d0 - 1) : -1e30f;
            s[n8][2] = (d0 + 8 >= 0) ? s[n8][2] * 0.125f - (float)(d0 + 8) : -1e30f;
            s[n8][3] = (d0 + 7 >= 0) ? s[n8][3] * 0.125f - (float)(d0 + 7) : -1e30f;
            rmax0 = fmaxf(rmax0, fmaxf(s[n8][0], s[n8][1]));
            rmax1 = fmaxf(rmax1, fmaxf(s[n8][2], s[n8][3]));
        }
        rmax0 = fmaxf(rmax0, __shfl_xor_sync(0xffffffffu, rmax0, 1));
        rmax0 = fmaxf(rmax0, __shfl_xor_sync(0xffffffffu, rmax0, 2));
        rmax1 = fmaxf(rmax1, __shfl_xor_sync(0xffffffffu, rmax1, 1));
        rmax1 = fmaxf(rmax1, __shfl_xor_sync(0xffffffffu, rmax1, 2));

        const float mn0 = fmaxf(m0r, rmax0), mn1 = fmaxf(m1r, rmax1);
        const float c0 = __expf(m0r - mn0),  c1 = __expf(m1r - mn1);
        m0r = mn0; m1r = mn1;
        l0 *= c0;  l1 *= c1;
        #pragma unroll
        for (int n8 = 0; n8 < 8; n8++) {
            o[n8][0] *= c0; o[n8][1] *= c0;
            o[n8][2] *= c1; o[n8][3] *= c1;
        }
        float ps0 = 0.f, ps1 = 0.f;
        #pragma unroll
        for (int n8 = 0; n8 < 8; n8++) {
            s[n8][0] = __expf(s[n8][0] - mn0);
            s[n8][1] = __expf(s[n8][1] - mn0);
            s[n8][2] = __expf(s[n8][2] - mn1);
            s[n8][3] = __expf(s[n8][3] - mn1);
            ps0 += s[n8][0] + s[n8][1];
            ps1 += s[n8][2] + s[n8][3];
        }
        l0 += ps0; l1 += ps1;

        // ---- pack P into A fragments (C->A layout identity) ----
        unsigned ph[4][4];
        #pragma unroll
        for (int kc = 0; kc < 4; kc++) {
            ph[kc][0] = packh2(s[2 * kc][0],     s[2 * kc][1]);
            ph[kc][1] = packh2(s[2 * kc][2],     s[2 * kc][3]);
            ph[kc][2] = packh2(s[2 * kc + 1][0], s[2 * kc + 1][1]);
            ph[kc][3] = packh2(s[2 * kc + 1][2], s[2 * kc + 1][3]);
        }

        // ---- O += P V ----
        #pragma unroll
        for (int ng = 0; ng < 4; ng++) {
            #pragma unroll
            for (int kc = 0; kc < 4; kc++) {
                const int jr = kc * 16 + vrow_b;
                const int c16 = ng * 2 + vc16_b;
                const unsigned a = (unsigned)jr * 128u
                                 + (unsigned)((c16 ^ (jr & 7)) << 4);
                unsigned vh[4];
                ldsm_x4_t(vh[0], vh[1], vh[2], vh[3], uV + a);
                mma_f16(o[ng * 2],     ph[kc], vh[0], vh[1]);
                mma_f16(o[ng * 2 + 1], ph[kc], vh[2], vh[3]);
            }
        }
    }

    // ---- epilogue ----
    l0 += __shfl_xor_sync(0xffffffffu, l0, 1);
    l0 += __shfl_xor_sync(0xffffffffu, l0, 2);
    l1 += __shfl_xor_sync(0xffffffffu, l1, 1);
    l1 += __shfl_xor_sync(0xffffffffu, l1, 2);
    const float i0 = 1.f / l0, i1 = 1.f / l1;

    const int row0 = qt * 64 + warp * 16 + (lane >> 2);
    const int b = bh >> 4, h = bh & 15;
    float* base0 = g_A + ((size_t)b * TSEQ + row0) * D_MODEL + h * HD;
    float* base1 = base0 + 8 * D_MODEL;
    #pragma unroll
    for (int n8 = 0; n8 < 8; n8++) {
        const int col = n8 * 8 + (lane & 3) * 2;
        float2 v0, v1;
        v0.x = o[n8][0] * i0; v0.y = o[n8][1] * i0;
        v1.x = o[n8][2] * i1; v1.y = o[n8][3] * i1;
        *(float2*)(base0 + col) = v0;
        *(float2*)(base1 + col) = v1;
    }
}

// ---------------------------------------------------------------------------
extern "C" void kernel_launch(void* const* d_in, const int* in_sizes, int n_in,
                              void* d_out, int out_size)
{
    const float* x  = (const float*)d_in[0];
    const float* Wq = (const float*)d_in[1];
    const float* bq = (const float*)d_in[2];
    const float* Wk = (const float*)d_in[3];
    const float* bk = (const float*)d_in[4];
    const float* Wv = (const float*)d_in[5];
    const float* bv = (const float*)d_in[6];
    const float* Wo = (const float*)d_in[7];
    const float* bo = (const float*)d_in[8];
    float* out = (float*)d_out;

    dim3 ggrid(D_MODEL / 128, M_TOT / 128, 3);
    qkv_gemm_kernel<<<ggrid, 256>>>(x, Wq, bq, Wk, bk, Wv, bv);

    dim3 agrid(TSEQ / 64, BATCH * NHEADS);
    attn_mma_kernel<<<agrid, 128>>>();

    dim3 ogrid(D_MODEL / 128, M_TOT / 128);
    out_gemm_kernel<<<ogrid, 256>>>(Wo, bo, out);
}

// round 12
// speedup vs baseline: 1.1834x; 1.1834x over previous
#include <cuda_runtime.h>
#include <cuda_fp16.h>
#include <cstdint>

#define D_MODEL 1024
#define NHEADS  16
#define HD      64
#define BATCH   2
#define TSEQ    2048
#define M_TOT   (BATCH * TSEQ)   // 4096

// Scratch (allocation-free rule: __device__ globals).
__device__ float g_Q[BATCH * NHEADS * TSEQ * HD];
__device__ float g_K[BATCH * NHEADS * TSEQ * HD];
__device__ float g_V[BATCH * NHEADS * TSEQ * HD];
__device__ float g_A[BATCH * TSEQ * D_MODEL];

static __device__ __forceinline__ uint32_t smem_u32(const void* p) {
    uint32_t a;
    asm("{ .reg .u64 t; cvta.to.shared.u64 t, %1; cvt.u32.u64 %0, t; }"
        : "=r"(a) : "l"(p));
    return a;
}

__device__ __forceinline__ void ldsm_x4(unsigned& r0, unsigned& r1,
                                        unsigned& r2, unsigned& r3,
                                        unsigned addr)
{
    asm volatile("ldmatrix.sync.aligned.m8n8.x4.shared.b16 {%0,%1,%2,%3}, [%4];"
                 : "=r"(r0), "=r"(r1), "=r"(r2), "=r"(r3) : "r"(addr));
}

__device__ __forceinline__ void ldsm_x4_t(unsigned& r0, unsigned& r1,
                                          unsigned& r2, unsigned& r3,
                                          unsigned addr)
{
    asm volatile("ldmatrix.sync.aligned.m8n8.x4.trans.shared.b16 {%0,%1,%2,%3}, [%4];"
                 : "=r"(r0), "=r"(r1), "=r"(r2), "=r"(r3) : "r"(addr));
}

__device__ __forceinline__ void mma_f16(float* d, const unsigned* a,
                                        unsigned b0, unsigned b1)
{
    asm volatile(
        "mma.sync.aligned.m16n8k16.row.col.f32.f16.f16.f32 "
        "{%0,%1,%2,%3}, {%4,%5,%6,%7}, {%8,%9}, {%0,%1,%2,%3};"
        : "+f"(d[0]), "+f"(d[1]), "+f"(d[2]), "+f"(d[3])
        : "r"(a[0]), "r"(a[1]), "r"(a[2]), "r"(a[3]), "r"(b0), "r"(b1));
}

static __device__ __forceinline__ unsigned packh2(float x, float y)
{
    __half2 h = __floats2half2_rn(x, y);
    return *(unsigned*)&h;
}

// ===========================================================================
// Projection GEMMs: 2-term fp16 split.  Y = Xhi*W + Xlo*W  (W single fp16).
// Block 128x128x16, 256 threads (8 warps = 2m x 4n), warp tile 64x32.
// __launch_bounds__(256, 2): 2 CTAs/SM (caps regs at 128 — R10 showed 140
// regs halves occupancy and stalls the tensor pipe).
// A smem row: 80B = 32B hi | 32B lo | 16B pad (conflict-free ldmatrix).
// B smem row: 48B = 32B fp16 | 16B pad.
// ===========================================================================
#define AROW_BYTES 80
#define BROW_BYTES 48
#define A_STAGE (128 * AROW_BYTES)   // 10240
#define B_STAGE (128 * BROW_BYTES)   // 6144
#define SMEM_TOTAL (2 * A_STAGE + 2 * B_STAGE)   // 32768

// X: 8 fp32 -> 4 half2 hi + 4 half2 lo (residual)
__device__ __forceinline__ void cvt8_store_a(unsigned addr, float4 a, float4 b)
{
    float f[8] = {a.x, a.y, a.z, a.w, b.x, b.y, b.z, b.w};
    unsigned hi[4], lo[4];
    #pragma unroll
    for (int i = 0; i < 4; i++) {
        float x = f[2 * i], y = f[2 * i + 1];
        __half2 hp = __floats2half2_rn(x, y);
        float lx = x - __low2float(hp), ly = y - __high2float(hp);
        __half2 lp = __floats2half2_rn(lx, ly);
        hi[i] = *(unsigned*)&hp;
        lo[i] = *(unsigned*)&lp;
    }
    asm volatile("st.shared.v4.b32 [%0], {%1,%2,%3,%4};"
                 :: "r"(addr), "r"(hi[0]), "r"(hi[1]), "r"(hi[2]), "r"(hi[3]));
    asm volatile("st.shared.v4.b32 [%0], {%1,%2,%3,%4};"
                 :: "r"(addr + 32), "r"(lo[0]), "r"(lo[1]), "r"(lo[2]), "r"(lo[3]));
}

// W: 8 fp32 -> 4 half2
__device__ __forceinline__ void cvt8_store_b(unsigned addr, float4 a, float4 b)
{
    unsigned h0 = packh2(a.x, a.y), h1 = packh2(a.z, a.w);
    unsigned h2 = packh2(b.x, b.y), h3 = packh2(b.z, b.w);
    asm volatile("st.shared.v4.b32 [%0], {%1,%2,%3,%4};"
                 :: "r"(addr), "r"(h0), "r"(h1), "r"(h2), "r"(h3));
}

__device__ __forceinline__ void mma_core(
    const float* __restrict__ X, const float* __restrict__ W,
    int m0, int n0, char* smem, float acc[4][4][4])
{
    const int tid  = threadIdx.x;
    const int lane = tid & 31;
    const int warp = tid >> 5;
    const int wm0  = (warp >> 2) * 64;
    const int wn0  = (warp & 3) * 32;

    const int lrow  = tid >> 1;
    const int lhalf = tid & 1;

    const float* xp = X + (size_t)(m0 + lrow) * D_MODEL + lhalf * 8;
    const float* wp = W + (size_t)(n0 + lrow) * D_MODEL + lhalf * 8;

    const unsigned sAb = smem_u32(smem);
    const unsigned sBb = sAb + 2 * A_STAGE;

    const unsigned stA = sAb + lrow * AROW_BYTES + lhalf * 16;
    const unsigned stB = sBb + lrow * BROW_BYTES + lhalf * 16;

    const int arow  = lane & 15;
    const int acoff = (lane >> 4) << 4;
    const unsigned ldA = sAb + (unsigned)(wm0 + arow) * AROW_BYTES + acoff;
    const int brow  = (lane & 7) + ((lane >> 4) << 3);
    const int bcoff = ((lane >> 3) & 1) << 4;
    const unsigned ldB = sBb + (unsigned)(wn0 + brow) * BROW_BYTES + bcoff;

    {
        float4 x0 = *(const float4*)xp;
        float4 x1 = *(const float4*)(xp + 4);
        float4 w0 = *(const float4*)wp;
        float4 w1 = *(const float4*)(wp + 4);
        cvt8_store_a(stA, x0, x1);
        cvt8_store_b(stB, w0, w1);
    }
    __syncthreads();

    unsigned buf = 0;
    for (int k0 = 16; k0 <= D_MODEL; k0 += 16) {
        const bool more = (k0 < D_MODEL);
        float4 nx0, nx1, nw0, nw1;
        if (more) {
            nx0 = *(const float4*)(xp + k0);
            nx1 = *(const float4*)(xp + k0 + 4);
            nw0 = *(const float4*)(wp + k0);
            nw1 = *(const float4*)(wp + k0 + 4);
        }

        const unsigned offA = buf * A_STAGE;
        const unsigned offB = buf * B_STAGE;
        unsigned b0[4], b1[4];
        ldsm_x4(b0[0], b0[1], b0[2], b0[3], ldB + offB);                   // n0,n1
        ldsm_x4(b1[0], b1[1], b1[2], b1[3], ldB + offB + 16 * BROW_BYTES); // n2,n3

        #pragma unroll
        for (int mi = 0; mi < 4; mi++) {
            unsigned ah[4], al[4];
            const unsigned am = ldA + offA + (unsigned)(mi * 16) * AROW_BYTES;
            ldsm_x4(ah[0], ah[1], ah[2], ah[3], am);
            ldsm_x4(al[0], al[1], al[2], al[3], am + 32);
            mma_f16(acc[mi][0], ah, b0[0], b0[1]);
            mma_f16(acc[mi][0], al, b0[0], b0[1]);
            mma_f16(acc[mi][1], ah, b0[2], b0[3]);
            mma_f16(acc[mi][1], al, b0[2], b0[3]);
            mma_f16(acc[mi][2], ah, b1[0], b1[1]);
            mma_f16(acc[mi][2], al, b1[0], b1[1]);
            mma_f16(acc[mi][3], ah, b1[2], b1[3]);
            mma_f16(acc[mi][3], al, b1[2], b1[3]);
        }

        if (more) {
            cvt8_store_a(stA + (buf ^ 1u) * A_STAGE, nx0, nx1);
            cvt8_store_b(stB + (buf ^ 1u) * B_STAGE, nw0, nw1);
            __syncthreads();
            buf ^= 1u;
        }
    }
}

__global__ __launch_bounds__(256, 2)
void qkv_gemm_kernel(const float* __restrict__ X,
                     const float* __restrict__ Wq, const float* __restrict__ bq,
                     const float* __restrict__ Wk, const float* __restrict__ bk,
                     const float* __restrict__ Wv, const float* __restrict__ bv)
{
    __shared__ __align__(16) char smem[SMEM_TOTAL];

    const float* W; const float* bias; float* dst;
    if (blockIdx.z == 0)      { W = Wq; bias = bq; dst = g_Q; }
    else if (blockIdx.z == 1) { W = Wk; bias = bk; dst = g_K; }
    else                      { W = Wv; bias = bv; dst = g_V; }

    const int m0 = blockIdx.y * 128, n0 = blockIdx.x * 128;
    float acc[4][4][4];
    #pragma unroll
    for (int i = 0; i < 4; i++)
        #pragma unroll
        for (int j = 0; j < 4; j++)
            #pragma unroll
            for (int r = 0; r < 4; r++) acc[i][j][r] = 0.f;

    mma_core(X, W, m0, n0, smem, acc);

    const int lane = threadIdx.x & 31, warp = threadIdx.x >> 5;
    const int wm0 = (warp >> 2) * 64, wn0 = (warp & 3) * 32;
    const int g = lane >> 2, t = lane & 3;

    #pragma unroll
    for (int n8 = 0; n8 < 4; n8++) {
        const int n = n0 + wn0 + n8 * 8 + 2 * t;
        const float bx = bias[n], by = bias[n + 1];
        const int h = n >> 6, d = n & 63;
        #pragma unroll
        for (int mi = 0; mi < 4; mi++) {
            #pragma unroll
            for (int half = 0; half < 2; half++) {
                const int m = m0 + wm0 + mi * 16 + g + half * 8;
                const int b = m >> 11, tt = m & (TSEQ - 1);
                float2 v;
                v.x = acc[mi][n8][2 * half + 0] + bx;
                v.y = acc[mi][n8][2 * half + 1] + by;
                *(float2*)&dst[(((size_t)b * NHEADS + h) * TSEQ + tt) * HD + d] = v;
            }
        }
    }
}

__global__ __launch_bounds__(256, 2)
void out_gemm_kernel(const float* __restrict__ Wo, const float* __restrict__ bo,
                     float* __restrict__ Y)
{
    __shared__ __align__(16) char smem[SMEM_TOTAL];

    const int m0 = blockIdx.y * 128, n0 = blockIdx.x * 128;
    float acc[4][4][4];
    #pragma unroll
    for (int i = 0; i < 4; i++)
        #pragma unroll
        for (int j = 0; j < 4; j++)
            #pragma unroll
            for (int r = 0; r < 4; r++) acc[i][j][r] = 0.f;

    mma_core(g_A, Wo, m0, n0, smem, acc);

    const int lane = threadIdx.x & 31, warp = threadIdx.x >> 5;
    const int wm0 = (warp >> 2) * 64, wn0 = (warp & 3) * 32;
    const int g = lane >> 2, t = lane & 3;

    #pragma unroll
    for (int n8 = 0; n8 < 4; n8++) {
        const int n = n0 + wn0 + n8 * 8 + 2 * t;
        const float bx = bo[n], by = bo[n + 1];
        #pragma unroll
        for (int mi = 0; mi < 4; mi++) {
            #pragma unroll
            for (int half = 0; half < 2; half++) {
                const int m = m0 + wm0 + mi * 16 + g + half * 8;
                float2 v;
                v.x = acc[mi][n8][2 * half + 0] + bx;
                v.y = acc[mi][n8][2 * half + 1] + by;
                *(float2*)&Y[(size_t)m * D_MODEL + n] = v;
            }
        }
    }
}

// ===========================================================================
// MMA flash-attention, single fp16 (errors ~1e-4, harmless through softmax).
// grid (T/64=32, B*H=32), 128 threads = 4 warps; warp w owns 16 query rows.
// Key tiles jt in [qt-2, qt] (decay -(i-j): delta >= 129 underflows to 0,
// identical to reference). smem: 64x64 fp16 tiles, 128B rows, SW128 swizzle.
// ===========================================================================

static __device__ __forceinline__ void cvt_store32h(
    uint32_t buf, int row, int half, const float* gp)
{
    uint32_t base_off = (uint32_t)row * 128u + (uint32_t)half * 64u;
    #pragma unroll
    for (int i = 0; i < 4; i++) {
        float4 va = *(const float4*)(gp + i * 8);
        float4 vb = *(const float4*)(gp + i * 8 + 4);
        unsigned h0 = packh2(va.x, va.y), h1 = packh2(va.z, va.w);
        unsigned h2 = packh2(vb.x, vb.y), h3 = packh2(vb.z, vb.w);
        uint32_t off = base_off + (uint32_t)i * 16u;
        uint32_t sw = off ^ ((off >> 3) & 0x70u);
        asm volatile("st.shared.v4.b32 [%0], {%1,%2,%3,%4};"
                     :: "r"(buf + sw), "r"(h0), "r"(h1), "r"(h2), "r"(h3));
    }
}

__global__ __launch_bounds__(128)
void attn_mma_kernel()
{
    __shared__ __align__(16) char sQ[8192];
    __shared__ __align__(16) char sK[8192];
    __shared__ __align__(16) char sV[8192];

    const int tid  = threadIdx.x;
    const int lane = tid & 31;
    const int warp = tid >> 5;
    const int qt   = blockIdx.x;
    const int bh   = blockIdx.y;

    const uint32_t uQ = smem_u32(sQ);
    const uint32_t uK = smem_u32(sK);
    const uint32_t uV = smem_u32(sV);

    const float* Qg = g_Q + (size_t)bh * TSEQ * HD;
    const float* Kg = g_K + (size_t)bh * TSEQ * HD;
    const float* Vg = g_V + (size_t)bh * TSEQ * HD;

    const int lrow  = tid >> 1;   // 0..63
    const int lhalf = tid & 1;

    // ---- stage Q tile, load Q fragments (held in regs for all ktiles) ----
    cvt_store32h(uQ, lrow, lhalf,
                 Qg + ((size_t)qt * 64 + lrow) * HD + lhalf * 32);
    __syncthreads();

    unsigned qh[4][4];
    {
        const int qrow = warp * 16 + (lane & 15);
        const int sel  = qrow & 7;
        #pragma unroll
        for (int ks = 0; ks < 4; ks++) {
            const int c16 = ks * 2 + (lane >> 4);
            const unsigned a = (unsigned)qrow * 128u + (unsigned)((c16 ^ sel) << 4);
            ldsm_x4(qh[ks][0], qh[ks][1], qh[ks][2], qh[ks][3], uQ + a);
        }
    }

    // ldmatrix lane geometry for K (no trans) and V (trans)
    const int krow_b = (lane & 7) + ((lane >> 4) << 3);
    const int kc16_b = (lane >> 3) & 1;
    const int vrow_b = (lane & 7) + (((lane >> 3) & 1) << 3);
    const int vc16_b = lane >> 4;

    float o[8][4];
    #pragma unroll
    for (int i = 0; i < 8; i++)
        #pragma unroll
        for (int r = 0; r < 4; r++) o[i][r] = 0.f;
    float m0r = -1e30f, m1r = -1e30f, l0 = 0.f, l1 = 0.f;

    const int jt0 = (qt >= 2) ? (qt - 2) : 0;
    for (int jt = jt0; jt <= qt; jt++) {
        __syncthreads();
        cvt_store32h(uK, lrow, lhalf,
                     Kg + ((size_t)jt * 64 + lrow) * HD + lhalf * 32);
        cvt_store32h(uV, lrow, lhalf,
                     Vg + ((size_t)jt * 64 + lrow) * HD + lhalf * 32);
        __syncthreads();

        // ---- S = Q K^T ----
        float s[8][4];
        #pragma unroll
        for (int i = 0; i < 8; i++)
            #pragma unroll
            for (int r = 0; r < 4; r++) s[i][r] = 0.f;

        #pragma unroll
        for (int ng = 0; ng < 4; ng++) {
            #pragma unroll
            for (int ks = 0; ks < 4; ks++) {
                const int jr = ng * 16 + krow_b;
                const int c16 = ks * 2 + kc16_b;
                const unsigned a = (unsigned)jr * 128u
                                 + (unsigned)((c16 ^ (jr & 7)) << 4);
                unsigned kh[4];
                ldsm_x4(kh[0], kh[1], kh[2], kh[3], uK + a);
                mma_f16(s[ng * 2],     qh[ks], kh[0], kh[1]);
                mma_f16(s[ng * 2 + 1], qh[ks], kh[2], kh[3]);
            }
        }

        // ---- softmax (online) ----
        const int dbase = (qt - jt) * 64 + warp * 16 + (lane >> 2);
        float rmax0 = -1e30f, rmax1 = -1e30f;
        #pragma unroll
        for (int n8 = 0; n8 < 8; n8++) {
            const int d0 = dbase - (n8 * 8 + (lane & 3) * 2);
            s[n8][0] = (d0     >= 0) ? s[n8][0] * 0.125f - (float)d0       : -1e30f;
            s[n8][1] = (d0 - 1 >= 0) ? s[n8][1] * 0.125f - (float)(d0 - 1) : -1e30f;
            s[n8][2] = (d0 + 8 >= 0) ? s[n8][2] * 0.125f - (float)(d0 + 8) : -1e30f;
            s[n8][3] = (d0 + 7 >= 0) ? s[n8][3] * 0.125f - (float)(d0 + 7) : -1e30f;
            rmax0 = fmaxf(rmax0, fmaxf(s[n8][0], s[n8][1]));
            rmax1 = fmaxf(rmax1, fmaxf(s[n8][2], s[n8][3]));
        }
        rmax0 = fmaxf(rmax0, __shfl_xor_sync(0xffffffffu, rmax0, 1));
        rmax0 = fmaxf(rmax0, __shfl_xor_sync(0xffffffffu, rmax0, 2));
        rmax1 = fmaxf(rmax1, __shfl_xor_sync(0xffffffffu, rmax1, 1));
        rmax1 = fmaxf(rmax1, __shfl_xor_sync(0xffffffffu, rmax1, 2));

        const float mn0 = fmaxf(m0r, rmax0), mn1 = fmaxf(m1r, rmax1);
        const float c0 = __expf(m0r - mn0),  c1 = __expf(m1r - mn1);
        m0r = mn0; m1r = mn1;
        l0 *= c0;  l1 *= c1;
        #pragma unroll
        for (int n8 = 0; n8 < 8; n8++) {
            o[n8][0] *= c0; o[n8][1] *= c0;
            o[n8][2] *= c1; o[n8][3] *= c1;
        }
        float ps0 = 0.f, ps1 = 0.f;
        #pragma unroll
        for (int n8 = 0; n8 < 8; n8++) {
            s[n8][0] = __expf(s[n8][0] - mn0);
            s[n8][1] = __expf(s[n8][1] - mn0);
            s[n8][2] = __expf(s[n8][2] - mn1);
            s[n8][3] = __expf(s[n8][3] - mn1);
            ps0 += s[n8][0] + s[n8][1];
            ps1 += s[n8][2] + s[n8][3];
        }
        l0 += ps0; l1 += ps1;

        // ---- pack P into A fragments (C->A layout identity) ----
        unsigned ph[4][4];
        #pragma unroll
        for (int kc = 0; kc < 4; kc++) {
            ph[kc][0] = packh2(s[2 * kc][0],     s[2 * kc][1]);
            ph[kc][1] = packh2(s[2 * kc][2],     s[2 * kc][3]);
            ph[kc][2] = packh2(s[2 * kc + 1][0], s[2 * kc + 1][1]);
            ph[kc][3] = packh2(s[2 * kc + 1][2], s[2 * kc + 1][3]);
        }

        // ---- O += P V ----
        #pragma unroll
        for (int ng = 0; ng < 4; ng++) {
            #pragma unroll
            for (int kc = 0; kc < 4; kc++) {
                const int jr = kc * 16 + vrow_b;
                const int c16 = ng * 2 + vc16_b;
                const unsigned a = (unsigned)jr * 128u
                                 + (unsigned)((c16 ^ (jr & 7)) << 4);
                unsigned vh[4];
                ldsm_x4_t(vh[0], vh[1], vh[2], vh[3], uV + a);
                mma_f16(o[ng * 2],     ph[kc], vh[0], vh[1]);
                mma_f16(o[ng * 2 + 1], ph[kc], vh[2], vh[3]);
            }
        }
    }

    // ---- epilogue ----
    l0 += __shfl_xor_sync(0xffffffffu, l0, 1);
    l0 += __shfl_xor_sync(0xffffffffu, l0, 2);
    l1 += __shfl_xor_sync(0xffffffffu, l1, 1);
    l1 += __shfl_xor_sync(0xffffffffu, l1, 2);
    const float i0 = 1.f / l0, i1 = 1.f / l1;

    const int row0 = qt * 64 + warp * 16 + (lane >> 2);
    const int b = bh >> 4, h = bh & 15;
    float* base0 = g_A + ((size_t)b * TSEQ + row0) * D_MODEL + h * HD;
    float* base1 = base0 + 8 * D_MODEL;
    #pragma unroll
    for (int n8 = 0; n8 < 8; n8++) {
        const int col = n8 * 8 + (lane & 3) * 2;
        float2 v0, v1;
        v0.x = o[n8][0] * i0; v0.y = o[n8][1] * i0;
        v1.x = o[n8][2] * i1; v1.y = o[n8][3] * i1;
        *(float2*)(base0 + col) = v0;
        *(float2*)(base1 + col) = v1;
    }
}

// ---------------------------------------------------------------------------
extern "C" void kernel_launch(void* const* d_in, const int* in_sizes, int n_in,
                              void* d_out, int out_size)
{
    const float* x  = (const float*)d_in[0];
    const float* Wq = (const float*)d_in[1];
    const float* bq = (const float*)d_in[2];
    const float* Wk = (const float*)d_in[3];
    const float* bk = (const float*)d_in[4];
    const float* Wv = (const float*)d_in[5];
    const float* bv = (const float*)d_in[6];
    const float* Wo = (const float*)d_in[7];
    const float* bo = (const float*)d_in[8];
    float* out = (float*)d_out;

    dim3 ggrid(D_MODEL / 128, M_TOT / 128, 3);
    qkv_gemm_kernel<<<ggrid, 256>>>(x, Wq, bq, Wk, bk, Wv, bv);

    dim3 agrid(TSEQ / 64, BATCH * NHEADS);
    attn_mma_kernel<<<agrid, 128>>>();

    dim3 ogrid(D_MODEL / 128, M_TOT / 128);
    out_gemm_kernel<<<ogrid, 256>>>(Wo, bo, out);
}

// round 13
// speedup vs baseline: 1.3925x; 1.1767x over previous
#include <cuda_runtime.h>
#include <cuda_fp16.h>
#include <cstdint>

#define D_MODEL 1024
#define NHEADS  16
#define HD      64
#define BATCH   2
#define TSEQ    2048
#define M_TOT   (BATCH * TSEQ)   // 4096

// Scratch (allocation-free rule: __device__ globals).
__device__ float g_Q[BATCH * NHEADS * TSEQ * HD];
__device__ float g_K[BATCH * NHEADS * TSEQ * HD];
__device__ float g_V[BATCH * NHEADS * TSEQ * HD];
__device__ float g_A[BATCH * TSEQ * D_MODEL];

static __device__ __forceinline__ uint32_t smem_u32(const void* p) {
    uint32_t a;
    asm("{ .reg .u64 t; cvta.to.shared.u64 t, %1; cvt.u32.u64 %0, t; }"
        : "=r"(a) : "l"(p));
    return a;
}

__device__ __forceinline__ void ldsm_x4(unsigned& r0, unsigned& r1,
                                        unsigned& r2, unsigned& r3,
                                        unsigned addr)
{
    asm volatile("ldmatrix.sync.aligned.m8n8.x4.shared.b16 {%0,%1,%2,%3}, [%4];"
                 : "=r"(r0), "=r"(r1), "=r"(r2), "=r"(r3) : "r"(addr));
}

__device__ __forceinline__ void ldsm_x4_t(unsigned& r0, unsigned& r1,
                                          unsigned& r2, unsigned& r3,
                                          unsigned addr)
{
    asm volatile("ldmatrix.sync.aligned.m8n8.x4.trans.shared.b16 {%0,%1,%2,%3}, [%4];"
                 : "=r"(r0), "=r"(r1), "=r"(r2), "=r"(r3) : "r"(addr));
}

__device__ __forceinline__ void mma_f16(float* d, const unsigned* a,
                                        unsigned b0, unsigned b1)
{
    asm volatile(
        "mma.sync.aligned.m16n8k16.row.col.f32.f16.f16.f32 "
        "{%0,%1,%2,%3}, {%4,%5,%6,%7}, {%8,%9}, {%0,%1,%2,%3};"
        : "+f"(d[0]), "+f"(d[1]), "+f"(d[2]), "+f"(d[3])
        : "r"(a[0]), "r"(a[1]), "r"(a[2]), "r"(a[3]), "r"(b0), "r"(b1));
}

static __device__ __forceinline__ unsigned packh2(float x, float y)
{
    __half2 h = __floats2half2_rn(x, y);
    return *(unsigned*)&h;
}

// ===========================================================================
// Projection GEMMs: single fp16 x single fp16 (rel err ~2e-4/GEMM; composite
// kernel error ~4e-4 < 1e-3 gate). Block 128x128x16, 256 threads (8 warps =
// 2m x 4n), warp tile 64x32. __launch_bounds__(256, 2) keeps 2 CTAs/SM.
// Both operand rows: 48B = 32B fp16 (16 k-values) | 16B pad — the 48B-stride
// ldmatrix phase pattern is conflict-free (addresses mod 128 all distinct).
// ===========================================================================
#define ROW_BYTES 48
#define OP_STAGE (128 * ROW_BYTES)            // 6144
#define SMEM_TOTAL (4 * OP_STAGE)             // A0,A1,B0,B1 = 24576

// 8 fp32 -> 4 half2, one STS.128
__device__ __forceinline__ void cvt8_store(unsigned addr, float4 a, float4 b)
{
    unsigned h0 = packh2(a.x, a.y), h1 = packh2(a.z, a.w);
    unsigned h2 = packh2(b.x, b.y), h3 = packh2(b.z, b.w);
    asm volatile("st.shared.v4.b32 [%0], {%1,%2,%3,%4};"
                 :: "r"(addr), "r"(h0), "r"(h1), "r"(h2), "r"(h3));
}

__device__ __forceinline__ void mma_core(
    const float* __restrict__ X, const float* __restrict__ W,
    int m0, int n0, char* smem, float acc[4][4][4])
{
    const int tid  = threadIdx.x;
    const int lane = tid & 31;
    const int warp = tid >> 5;
    const int wm0  = (warp >> 2) * 64;
    const int wn0  = (warp & 3) * 32;

    const int lrow  = tid >> 1;
    const int lhalf = tid & 1;

    const float* xp = X + (size_t)(m0 + lrow) * D_MODEL + lhalf * 8;
    const float* wp = W + (size_t)(n0 + lrow) * D_MODEL + lhalf * 8;

    const unsigned sAb = smem_u32(smem);
    const unsigned sBb = sAb + 2 * OP_STAGE;

    const unsigned stA = sAb + lrow * ROW_BYTES + lhalf * 16;
    const unsigned stB = sBb + lrow * ROW_BYTES + lhalf * 16;

    const int arow  = lane & 15;
    const int acoff = (lane >> 4) << 4;
    const unsigned ldA = sAb + (unsigned)(wm0 + arow) * ROW_BYTES + acoff;
    const int brow  = (lane & 7) + ((lane >> 4) << 3);
    const int bcoff = ((lane >> 3) & 1) << 4;
    const unsigned ldB = sBb + (unsigned)(wn0 + brow) * ROW_BYTES + bcoff;

    {
        float4 x0 = *(const float4*)xp;
        float4 x1 = *(const float4*)(xp + 4);
        float4 w0 = *(const float4*)wp;
        float4 w1 = *(const float4*)(wp + 4);
        cvt8_store(stA, x0, x1);
        cvt8_store(stB, w0, w1);
    }
    __syncthreads();

    unsigned buf = 0;
    for (int k0 = 16; k0 <= D_MODEL; k0 += 16) {
        const bool more = (k0 < D_MODEL);
        float4 nx0, nx1, nw0, nw1;
        if (more) {
            nx0 = *(const float4*)(xp + k0);
            nx1 = *(const float4*)(xp + k0 + 4);
            nw0 = *(const float4*)(wp + k0);
            nw1 = *(const float4*)(wp + k0 + 4);
        }

        const unsigned off = buf * OP_STAGE;
        unsigned b0[4], b1[4];
        ldsm_x4(b0[0], b0[1], b0[2], b0[3], ldB + off);                   // n0,n1
        ldsm_x4(b1[0], b1[1], b1[2], b1[3], ldB + off + 16 * ROW_BYTES);  // n2,n3

        #pragma unroll
        for (int mi = 0; mi < 4; mi++) {
            unsigned ah[4];
            ldsm_x4(ah[0], ah[1], ah[2], ah[3],
                    ldA + off + (unsigned)(mi * 16) * ROW_BYTES);
            mma_f16(acc[mi][0], ah, b0[0], b0[1]);
            mma_f16(acc[mi][1], ah, b0[2], b0[3]);
            mma_f16(acc[mi][2], ah, b1[0], b1[1]);
            mma_f16(acc[mi][3], ah, b1[2], b1[3]);
        }

        if (more) {
            cvt8_store(stA + (buf ^ 1u) * OP_STAGE, nx0, nx1);
            cvt8_store(stB + (buf ^ 1u) * OP_STAGE, nw0, nw1);
            __syncthreads();
            buf ^= 1u;
        }
    }
}

__global__ __launch_bounds__(256, 2)
void qkv_gemm_kernel(const float* __restrict__ X,
                     const float* __restrict__ Wq, const float* __restrict__ bq,
                     const float* __restrict__ Wk, const float* __restrict__ bk,
                     const float* __restrict__ Wv, const float* __restrict__ bv)
{
    __shared__ __align__(16) char smem[SMEM_TOTAL];

    const float* W; const float* bias; float* dst;
    if (blockIdx.z == 0)      { W = Wq; bias = bq; dst = g_Q; }
    else if (blockIdx.z == 1) { W = Wk; bias = bk; dst = g_K; }
    else                      { W = Wv; bias = bv; dst = g_V; }

    const int m0 = blockIdx.y * 128, n0 = blockIdx.x * 128;
    float acc[4][4][4];
    #pragma unroll
    for (int i = 0; i < 4; i++)
        #pragma unroll
        for (int j = 0; j < 4; j++)
            #pragma unroll
            for (int r = 0; r < 4; r++) acc[i][j][r] = 0.f;

    mma_core(X, W, m0, n0, smem, acc);

    const int lane = threadIdx.x & 31, warp = threadIdx.x >> 5;
    const int wm0 = (warp >> 2) * 64, wn0 = (warp & 3) * 32;
    const int g = lane >> 2, t = lane & 3;

    #pragma unroll
    for (int n8 = 0; n8 < 4; n8++) {
        const int n = n0 + wn0 + n8 * 8 + 2 * t;
        const float bx = bias[n], by = bias[n + 1];
        const int h = n >> 6, d = n & 63;
        #pragma unroll
        for (int mi = 0; mi < 4; mi++) {
            #pragma unroll
            for (int half = 0; half < 2; half++) {
                const int m = m0 + wm0 + mi * 16 + g + half * 8;
                const int b = m >> 11, tt = m & (TSEQ - 1);
                float2 v;
                v.x = acc[mi][n8][2 * half + 0] + bx;
                v.y = acc[mi][n8][2 * half + 1] + by;
                *(float2*)&dst[(((size_t)b * NHEADS + h) * TSEQ + tt) * HD + d] = v;
            }
        }
    }
}

__global__ __launch_bounds__(256, 2)
void out_gemm_kernel(const float* __restrict__ Wo, const float* __restrict__ bo,
                     float* __restrict__ Y)
{
    __shared__ __align__(16) char smem[SMEM_TOTAL];

    const int m0 = blockIdx.y * 128, n0 = blockIdx.x * 128;
    float acc[4][4][4];
    #pragma unroll
    for (int i = 0; i < 4; i++)
        #pragma unroll
        for (int j = 0; j < 4; j++)
            #pragma unroll
            for (int r = 0; r < 4; r++) acc[i][j][r] = 0.f;

    mma_core(g_A, Wo, m0, n0, smem, acc);

    const int lane = threadIdx.x & 31, warp = threadIdx.x >> 5;
    const int wm0 = (warp >> 2) * 64, wn0 = (warp & 3) * 32;
    const int g = lane >> 2, t = lane & 3;

    #pragma unroll
    for (int n8 = 0; n8 < 4; n8++) {
        const int n = n0 + wn0 + n8 * 8 + 2 * t;
        const float bx = bo[n], by = bo[n + 1];
        #pragma unroll
        for (int mi = 0; mi < 4; mi++) {
            #pragma unroll
            for (int half = 0; half < 2; half++) {
                const int m = m0 + wm0 + mi * 16 + g + half * 8;
                float2 v;
                v.x = acc[mi][n8][2 * half + 0] + bx;
                v.y = acc[mi][n8][2 * half + 1] + by;
                *(float2*)&Y[(size_t)m * D_MODEL + n] = v;
            }
        }
    }
}

// ===========================================================================
// MMA flash-attention, single fp16 (unchanged from 331us best).
// grid (T/64=32, B*H=32), 128 threads = 4 warps; warp w owns 16 query rows.
// Key tiles jt in [qt-2, qt] (decay -(i-j): delta >= 129 underflows to 0,
// identical to reference). smem: 64x64 fp16 tiles, 128B rows, SW128 swizzle.
// ===========================================================================

static __device__ __forceinline__ void cvt_store32h(
    uint32_t buf, int row, int half, const float* gp)
{
    uint32_t base_off = (uint32_t)row * 128u + (uint32_t)half * 64u;
    #pragma unroll
    for (int i = 0; i < 4; i++) {
        float4 va = *(const float4*)(gp + i * 8);
        float4 vb = *(const float4*)(gp + i * 8 + 4);
        unsigned h0 = packh2(va.x, va.y), h1 = packh2(va.z, va.w);
        unsigned h2 = packh2(vb.x, vb.y), h3 = packh2(vb.z, vb.w);
        uint32_t off = base_off + (uint32_t)i * 16u;
        uint32_t sw = off ^ ((off >> 3) & 0x70u);
        asm volatile("st.shared.v4.b32 [%0], {%1,%2,%3,%4};"
                     :: "r"(buf + sw), "r"(h0), "r"(h1), "r"(h2), "r"(h3));
    }
}

__global__ __launch_bounds__(128)
void attn_mma_kernel()
{
    __shared__ __align__(16) char sQ[8192];
    __shared__ __align__(16) char sK[8192];
    __shared__ __align__(16) char sV[8192];

    const int tid  = threadIdx.x;
    const int lane = tid & 31;
    const int warp = tid >> 5;
    const int qt   = blockIdx.x;
    const int bh   = blockIdx.y;

    const uint32_t uQ = smem_u32(sQ);
    const uint32_t uK = smem_u32(sK);
    const uint32_t uV = smem_u32(sV);

    const float* Qg = g_Q + (size_t)bh * TSEQ * HD;
    const float* Kg = g_K + (size_t)bh * TSEQ * HD;
    const float* Vg = g_V + (size_t)bh * TSEQ * HD;

    const int lrow  = tid >> 1;   // 0..63
    const int lhalf = tid & 1;

    // ---- stage Q tile, load Q fragments (held in regs for all ktiles) ----
    cvt_store32h(uQ, lrow, lhalf,
                 Qg + ((size_t)qt * 64 + lrow) * HD + lhalf * 32);
    __syncthreads();

    unsigned qh[4][4];
    {
        const int qrow = warp * 16 + (lane & 15);
        const int sel  = qrow & 7;
        #pragma unroll
        for (int ks = 0; ks < 4; ks++) {
            const int c16 = ks * 2 + (lane >> 4);
            const unsigned a = (unsigned)qrow * 128u + (unsigned)((c16 ^ sel) << 4);
            ldsm_x4(qh[ks][0], qh[ks][1], qh[ks][2], qh[ks][3], uQ + a);
        }
    }

    // ldmatrix lane geometry for K (no trans) and V (trans)
    const int krow_b = (lane & 7) + ((lane >> 4) << 3);
    const int kc16_b = (lane >> 3) & 1;
    const int vrow_b = (lane & 7) + (((lane >> 3) & 1) << 3);
    const int vc16_b = lane >> 4;

    float o[8][4];
    #pragma unroll
    for (int i = 0; i < 8; i++)
        #pragma unroll
        for (int r = 0; r < 4; r++) o[i][r] = 0.f;
    float m0r = -1e30f, m1r = -1e30f, l0 = 0.f, l1 = 0.f;

    const int jt0 = (qt >= 2) ? (qt - 2) : 0;
    for (int jt = jt0; jt <= qt; jt++) {
        __syncthreads();
        cvt_store32h(uK, lrow, lhalf,
                     Kg + ((size_t)jt * 64 + lrow) * HD + lhalf * 32);
        cvt_store32h(uV, lrow, lhalf,
                     Vg + ((size_t)jt * 64 + lrow) * HD + lhalf * 32);
        __syncthreads();

        // ---- S = Q K^T ----
        float s[8][4];
        #pragma unroll
        for (int i = 0; i < 8; i++)
            #pragma unroll
            for (int r = 0; r < 4; r++) s[i][r] = 0.f;

        #pragma unroll
        for (int ng = 0; ng < 4; ng++) {
            #pragma unroll
            for (int ks = 0; ks < 4; ks++) {
                const int jr = ng * 16 + krow_b;
                const int c16 = ks * 2 + kc16_b;
                const unsigned a = (unsigned)jr * 128u
                                 + (unsigned)((c16 ^ (jr & 7)) << 4);
                unsigned kh[4];
                ldsm_x4(kh[0], kh[1], kh[2], kh[3], uK + a);
                mma_f16(s[ng * 2],     qh[ks], kh[0], kh[1]);
                mma_f16(s[ng * 2 + 1], qh[ks], kh[2], kh[3]);
            }
        }

        // ---- softmax (online) ----
        const int dbase = (qt - jt) * 64 + warp * 16 + (lane >> 2);
        float rmax0 = -1e30f, rmax1 = -1e30f;
        #pragma unroll
        for (int n8 = 0; n8 < 8; n8++) {
            const int d0 = dbase - (n8 * 8 + (lane & 3) * 2);
            s[n8][0] = (d0     >= 0) ? s[n8][0] * 0.125f - (float)d0       : -1e30f;
            s[n8][1] = (d0 - 1 >= 0) ? s[n8][1] * 0.125f - (float)(d0 - 1) : -1e30f;
            s[n8][2] = (d0 + 8 >= 0) ? s[n8][2] * 0.125f - (float)(d0 + 8) : -1e30f;
            s[n8][3] = (d0 + 7 >= 0) ? s[n8][3] * 0.125f - (float)(d0 + 7) : -1e30f;
            rmax0 = fmaxf(rmax0, fmaxf(s[n8][0], s[n8][1]));
            rmax1 = fmaxf(rmax1, fmaxf(s[n8][2], s[n8][3]));
        }
        rmax0 = fmaxf(rmax0, __shfl_xor_sync(0xffffffffu, rmax0, 1));
        rmax0 = fmaxf(rmax0, __shfl_xor_sync(0xffffffffu, rmax0, 2));
        rmax1 = fmaxf(rmax1, __shfl_xor_sync(0xffffffffu, rmax1, 1));
        rmax1 = fmaxf(rmax1, __shfl_xor_sync(0xffffffffu, rmax1, 2));

        const float mn0 = fmaxf(m0r, rmax0), mn1 = fmaxf(m1r, rmax1);
        const float c0 = __expf(m0r - mn0),  c1 = __expf(m1r - mn1);
        m0r = mn0; m1r = mn1;
        l0 *= c0;  l1 *= c1;
        #pragma unroll
        for (int n8 = 0; n8 < 8; n8++) {
            o[n8][0] *= c0; o[n8][1] *= c0;
            o[n8][2] *= c1; o[n8][3] *= c1;
        }
        float ps0 = 0.f, ps1 = 0.f;
        #pragma unroll
        for (int n8 = 0; n8 < 8; n8++) {
            s[n8][0] = __expf(s[n8][0] - mn0);
            s[n8][1] = __expf(s[n8][1] - mn0);
            s[n8][2] = __expf(s[n8][2] - mn1);
            s[n8][3] = __expf(s[n8][3] - mn1);
            ps0 += s[n8][0] + s[n8][1];
            ps1 += s[n8][2] + s[n8][3];
        }
        l0 += ps0; l1 += ps1;

        // ---- pack P into A fragments (C->A layout identity) ----
        unsigned ph[4][4];
        #pragma unroll
        for (int kc = 0; kc < 4; kc++) {
            ph[kc][0] = packh2(s[2 * kc][0],     s[2 * kc][1]);
            ph[kc][1] = packh2(s[2 * kc][2],     s[2 * kc][3]);
            ph[kc][2] = packh2(s[2 * kc + 1][0], s[2 * kc + 1][1]);
            ph[kc][3] = packh2(s[2 * kc + 1][2], s[2 * kc + 1][3]);
        }

        // ---- O += P V ----
        #pragma unroll
        for (int ng = 0; ng < 4; ng++) {
            #pragma unroll
            for (int kc = 0; kc < 4; kc++) {
                const int jr = kc * 16 + vrow_b;
                const int c16 = ng * 2 + vc16_b;
                const unsigned a = (unsigned)jr * 128u
                                 + (unsigned)((c16 ^ (jr & 7)) << 4);
                unsigned vh[4];
                ldsm_x4_t(vh[0], vh[1], vh[2], vh[3], uV + a);
                mma_f16(o[ng * 2],     ph[kc], vh[0], vh[1]);
                mma_f16(o[ng * 2 + 1], ph[kc], vh[2], vh[3]);
            }
        }
    }

    // ---- epilogue ----
    l0 += __shfl_xor_sync(0xffffffffu, l0, 1);
    l0 += __shfl_xor_sync(0xffffffffu, l0, 2);
    l1 += __shfl_xor_sync(0xffffffffu, l1, 1);
    l1 += __shfl_xor_sync(0xffffffffu, l1, 2);
    const float i0 = 1.f / l0, i1 = 1.f / l1;

    const int row0 = qt * 64 + warp * 16 + (lane >> 2);
    const int b = bh >> 4, h = bh & 15;
    float* base0 = g_A + ((size_t)b * TSEQ + row0) * D_MODEL + h * HD;
    float* base1 = base0 + 8 * D_MODEL;
    #pragma unroll
    for (int n8 = 0; n8 < 8; n8++) {
        const int col = n8 * 8 + (lane & 3) * 2;
        float2 v0, v1;
        v0.x = o[n8][0] * i0; v0.y = o[n8][1] * i0;
        v1.x = o[n8][2] * i1; v1.y = o[n8][3] * i1;
        *(float2*)(base0 + col) = v0;
        *(float2*)(base1 + col) = v1;
    }
}

// ---------------------------------------------------------------------------
extern "C" void kernel_launch(void* const* d_in, const int* in_sizes, int n_in,
                              void* d_out, int out_size)
{
    const float* x  = (const float*)d_in[0];
    const float* Wq = (const float*)d_in[1];
    const float* bq = (const float*)d_in[2];
    const float* Wk = (const float*)d_in[3];
    const float* bk = (const float*)d_in[4];
    const float* Wv = (const float*)d_in[5];
    const float* bv = (const float*)d_in[6];
    const float* Wo = (const float*)d_in[7];
    const float* bo = (const float*)d_in[8];
    float* out = (float*)d_out;

    dim3 ggrid(D_MODEL / 128, M_TOT / 128, 3);
    qkv_gemm_kernel<<<ggrid, 256>>>(x, Wq, bq, Wk, bk, Wv, bv);

    dim3 agrid(TSEQ / 64, BATCH * NHEADS);
    attn_mma_kernel<<<agrid, 128>>>();

    dim3 ogrid(D_MODEL / 128, M_TOT / 128);
    out_gemm_kernel<<<ogrid, 256>>>(Wo, bo, out);
}